// round 2
// baseline (speedup 1.0000x reference)
#include <cuda_runtime.h>
#include <math.h>

#define HIDDEN 128
#define KQCH   384
#define HH     48
#define WW     64
#define HWP    (HH*WW)    // 3072
#define NB     4

// Scratch (allocation-free rule: __device__ globals)
__device__ float g_val[(size_t)NB*HIDDEN*HWP];
__device__ float g_scores[(size_t)NB*HWP*HWP];   // ~151 MB
__device__ float g_pval[(size_t)NB*HIDDEN*HWP];
__device__ float g_v2[(size_t)NB*HIDDEN*HWP];
__device__ float g_t1[(size_t)NB*HIDDEN*HWP];

__device__ __forceinline__ float lrelu(float x) { return x >= 0.f ? x : 0.2f * x; }

// ---------------------------------------------------------------------------
// Generic batched tiled SGEMM: C[M,N] = alpha * op(A) @ B   (+ epilogue)
//   TRANSA=false: A is [M,K] row-major (lda = K-stride)
//   TRANSA=true : A is [K,M] row-major (lda = M-stride)  -> C = A^T B
//   B is [K,N] row-major. Requires M%128==0, N%128==0, K%8==0.
//   epi: 0 = store, 1 = lrelu, 2 = Res + lrelu
// ---------------------------------------------------------------------------
template<bool TRANSA>
__global__ void __launch_bounds__(256) sgemm128(
    const float* __restrict__ A, const float* __restrict__ B,
    const float* __restrict__ Res, float* __restrict__ C,
    int M, int N, int K, int lda, int ldb, int ldc,
    long long sA, long long sB, long long sC,
    float alpha, int epi)
{
    __shared__ float As[8][128];
    __shared__ float Bs[8][128];

    int z = blockIdx.z;
    A += (long long)z * sA;
    B += (long long)z * sB;
    C += (long long)z * sC;
    if (Res) Res += (long long)z * sC;

    int m0 = blockIdx.y * 128, n0 = blockIdx.x * 128;
    int tid = threadIdx.x;
    int tx = tid & 15, ty = tid >> 4;

    float acc[8][8];
#pragma unroll
    for (int i = 0; i < 8; i++)
#pragma unroll
        for (int j = 0; j < 8; j++) acc[i][j] = 0.f;

    for (int k0 = 0; k0 < K; k0 += 8) {
        // B tile: 4 floats/thread, coalesced
        {
            int kk = tid >> 5, c = (tid & 31) * 4;
            float4 bv = *reinterpret_cast<const float4*>(
                &B[(long long)(k0 + kk) * ldb + n0 + c]);
            Bs[kk][c] = bv.x; Bs[kk][c + 1] = bv.y;
            Bs[kk][c + 2] = bv.z; Bs[kk][c + 3] = bv.w;
        }
        if (TRANSA) {
            int kk = tid >> 5, r = (tid & 31) * 4;
            float4 av = *reinterpret_cast<const float4*>(
                &A[(long long)(k0 + kk) * lda + m0 + r]);
            As[kk][r] = av.x; As[kk][r + 1] = av.y;
            As[kk][r + 2] = av.z; As[kk][r + 3] = av.w;
        } else {
            int r = tid >> 1, c = (tid & 1) * 4;
            float4 av = *reinterpret_cast<const float4*>(
                &A[(long long)(m0 + r) * lda + k0 + c]);
            As[c][r] = av.x; As[c + 1][r] = av.y;
            As[c + 2][r] = av.z; As[c + 3][r] = av.w;
        }
        __syncthreads();

#pragma unroll
        for (int kk = 0; kk < 8; kk++) {
            float a[8], b[8];
#pragma unroll
            for (int i = 0; i < 8; i++) a[i] = As[kk][ty * 8 + i];
#pragma unroll
            for (int j = 0; j < 8; j++) b[j] = Bs[kk][tx * 8 + j];
#pragma unroll
            for (int i = 0; i < 8; i++)
#pragma unroll
                for (int j = 0; j < 8; j++)
                    acc[i][j] = fmaf(a[i], b[j], acc[i][j]);
        }
        __syncthreads();
    }

#pragma unroll
    for (int i = 0; i < 8; i++) {
        int gi = m0 + ty * 8 + i;
#pragma unroll
        for (int j = 0; j < 8; j++) {
            int gj = n0 + tx * 8 + j;
            float vv = acc[i][j] * alpha;
            if (epi == 1) vv = lrelu(vv);
            else if (epi == 2) vv = Res[(long long)gi * ldc + gj] + lrelu(vv);
            C[(long long)gi * ldc + gj] = vv;
        }
    }
}

// ---------------------------------------------------------------------------
// Column softmax over key axis: S is [HW, HW] per batch, softmax over rows
// (dim k) for each column q. Thread-per-column; loads coalesced across warp.
// ---------------------------------------------------------------------------
__global__ void __launch_bounds__(256) softmax_col(float* __restrict__ S)
{
    int q = blockIdx.x * 256 + threadIdx.x;
    float* Sb = S + (long long)blockIdx.z * HWP * HWP;

    float m = -1e30f;
    for (int k = 0; k < HWP; k++)
        m = fmaxf(m, Sb[(long long)k * HWP + q]);

    float s = 0.f;
    for (int k = 0; k < HWP; k++)
        s += __expf(Sb[(long long)k * HWP + q] - m);

    float inv = 1.f / s;
    for (int k = 0; k < HWP; k++) {
        long long idx = (long long)k * HWP + q;
        Sb[idx] = __expf(Sb[idx] - m) * inv;
    }
}

// ---------------------------------------------------------------------------
// 3x3 conv (128->128 ch) as implicit GEMM over K = 9*128 = 1152.
// Block: all 128 out channels x 64 pixels (= exactly one image row, W=64).
// B-tile loader applies spatial shift + zero padding.
//   epi: 1 = lrelu, 2 = Res + lrelu
// ---------------------------------------------------------------------------
template<int DIL>
__global__ void __launch_bounds__(256) conv3x3_gemm(
    const float* __restrict__ in, const float* __restrict__ wt,
    const float* __restrict__ Res, float* __restrict__ out, int epi)
{
    __shared__ float As[8][128];
    __shared__ float Bs[8][64];

    int z = blockIdx.z;
    in  += (long long)z * HIDDEN * HWP;
    out += (long long)z * HIDDEN * HWP;
    const float* Rb = Res ? Res + (long long)z * HIDDEN * HWP : nullptr;

    int n0 = blockIdx.x * 64;
    int tid = threadIdx.x;
    int tx = tid & 15, ty = tid >> 4;

    float acc[8][4];
#pragma unroll
    for (int i = 0; i < 8; i++)
#pragma unroll
        for (int j = 0; j < 4; j++) acc[i][j] = 0.f;

    for (int k0 = 0; k0 < 1152; k0 += 8) {
        int kk = tid >> 5;
        int kglob = k0 + kk;
        int tap = kglob >> 7;       // 0..8   (k ordered as tap*128 + ic)
        int ic  = kglob & 127;
        int dy = (tap / 3 - 1) * DIL;
        int dx = (tap % 3 - 1) * DIL;

        // B tile: shifted input, 2 elems/thread
        {
            int c0 = (tid & 31) * 2;
#pragma unroll
            for (int u = 0; u < 2; u++) {
                int p = n0 + c0 + u;
                int y = p >> 6, x = p & 63;
                int yy = y + dy, xx = x + dx;
                float v = 0.f;
                if ((unsigned)yy < HH && (unsigned)xx < WW)
                    v = in[ic * HWP + yy * WW + xx];
                Bs[kk][c0 + u] = v;
            }
        }
        // A tile: weights OIHW -> A[oc, tap*128+ic], 4 elems/thread
        {
            int r0 = (tid & 31) * 4;
#pragma unroll
            for (int u = 0; u < 4; u++)
                As[kk][r0 + u] = wt[(r0 + u) * 1152 + ic * 9 + tap];
        }
        __syncthreads();

#pragma unroll
        for (int k2 = 0; k2 < 8; k2++) {
            float a[8], b[4];
#pragma unroll
            for (int i = 0; i < 8; i++) a[i] = As[k2][ty * 8 + i];
#pragma unroll
            for (int j = 0; j < 4; j++) b[j] = Bs[k2][tx * 4 + j];
#pragma unroll
            for (int i = 0; i < 8; i++)
#pragma unroll
                for (int j = 0; j < 4; j++)
                    acc[i][j] = fmaf(a[i], b[j], acc[i][j]);
        }
        __syncthreads();
    }

#pragma unroll
    for (int i = 0; i < 8; i++) {
        int gi = ty * 8 + i;
#pragma unroll
        for (int j = 0; j < 4; j++) {
            int gj = n0 + tx * 4 + j;
            float vv = acc[i][j];
            if (epi == 1) vv = lrelu(vv);
            else if (epi == 2) vv = Rb[(long long)gi * HWP + gj] + lrelu(vv);
            out[(long long)gi * HWP + gj] = vv;
        }
    }
}

// ---------------------------------------------------------------------------

extern "C" void kernel_launch(void* const* d_in, const int* in_sizes, int n_in,
                              void* d_out, int out_size)
{
    const float* k_in    = (const float*)d_in[0];  // [4,384,48,64]
    const float* q_in    = (const float*)d_in[1];  // [4,384,48,64]
    const float* v_in    = (const float*)d_in[2];  // [4,128,48,64]
    const float* w_value = (const float*)d_in[3];  // [128,128,1,1]
    const float* w_out   = (const float*)d_in[4];  // [128,128,3,3]
    const float* w_ff1   = (const float*)d_in[5];  // [128,128,3,3]
    const float* w_ff2   = (const float*)d_in[6];  // [128,128,3,3]
    float* out = (float*)d_out;

    float *val, *scores, *pval, *v2, *t1;
    cudaGetSymbolAddress((void**)&val,    g_val);
    cudaGetSymbolAddress((void**)&scores, g_scores);
    cudaGetSymbolAddress((void**)&pval,   g_pval);
    cudaGetSymbolAddress((void**)&v2,     g_v2);
    cudaGetSymbolAddress((void**)&t1,     g_t1);

    const long long sCHW = (long long)HIDDEN * HWP;   // 128*3072
    const long long sKQ  = (long long)KQCH * HWP;     // 384*3072
    const long long sSS  = (long long)HWP * HWP;      // 3072*3072

    // 1) val = w_value @ v   (1x1 conv), M=128 N=3072 K=128
    sgemm128<false><<<dim3(HWP / 128, 1, NB), 256>>>(
        w_value, v_in, nullptr, val,
        HIDDEN, HWP, HIDDEN, HIDDEN, HWP, HWP,
        0LL, sCHW, sCHW, 1.f, 0);

    // 2) scores = (k^T q) / sqrt(384), M=N=3072 K=384
    sgemm128<true><<<dim3(HWP / 128, HWP / 128, NB), 256>>>(
        k_in, q_in, nullptr, scores,
        HWP, HWP, KQCH, HWP, HWP, HWP,
        sKQ, sKQ, sSS, 0.05103103630798288f, 0);

    // 3) softmax over key axis (columns of the [k,q] matrix -> per-q over k)
    softmax_col<<<dim3(HWP / 256, 1, NB), 256>>>(scores);

    // 4) p_val = val @ p_attn, M=128 N=3072 K=3072
    sgemm128<false><<<dim3(HWP / 128, 1, NB), 256>>>(
        val, scores, nullptr, pval,
        HIDDEN, HWP, HWP, HWP, HWP, HWP,
        sCHW, sSS, sCHW, 1.f, 0);

    // 5) v2 = v + lrelu(conv3x3(p_val, w_out, pad=1))
    conv3x3_gemm<1><<<dim3(HWP / 64, 1, NB), 256>>>(pval, w_out, v_in, v2, 2);

    // 6) t1 = lrelu(conv3x3(v2, w_ff1, pad=2, dil=2))
    conv3x3_gemm<2><<<dim3(HWP / 64, 1, NB), 256>>>(v2, w_ff1, nullptr, t1, 1);

    // 7) out = v2 + lrelu(conv3x3(t1, w_ff2, pad=1))
    conv3x3_gemm<1><<<dim3(HWP / 64, 1, NB), 256>>>(t1, w_ff2, v2, out, 2);
}

// round 4
// speedup vs baseline: 1.9914x; 1.9914x over previous
#include <cuda_runtime.h>
#include <cstdint>
#include <math.h>

#define HIDDEN 128
#define KQCH   384
#define HH     48
#define WW     64
#define HWP    3072
#define NB     4
#define SCALE  0.05103103630798288f

// Scratch (allocation-free rule: __device__ globals)
__device__ float g_val[(size_t)NB*HIDDEN*HWP];
__device__ float g_pval[(size_t)NB*HIDDEN*HWP];
__device__ float g_v2[(size_t)NB*HIDDEN*HWP];
__device__ float g_t1[(size_t)NB*HIDDEN*HWP];

__device__ __forceinline__ float lrelu(float x) { return x >= 0.f ? x : 0.2f * x; }

// ---------------- PTX helpers (baseline ISA only: mma.sync + cp.async) -----
__device__ __forceinline__ uint32_t f2tf32(float f) {
    uint32_t u;
    asm("cvt.rna.tf32.f32 %0, %1;" : "=r"(u) : "f"(f));
    return u;
}

#define CP16(dst_u32, src_ptr) \
    asm volatile("cp.async.cg.shared.global [%0], [%1], 16;" \
        :: "r"(dst_u32), "l"(src_ptr))
#define CPCOMMIT() asm volatile("cp.async.commit_group;" ::: "memory")
#define CPWAIT(n)  asm volatile("cp.async.wait_group %0;" :: "n"(n) : "memory")

#define MMA8(c, a, b) \
    asm volatile( \
        "mma.sync.aligned.m16n8k8.row.col.f32.tf32.tf32.f32 " \
        "{%0,%1,%2,%3},{%4,%5,%6,%7},{%8,%9},{%0,%1,%2,%3};" \
        : "+f"((c)[0]), "+f"((c)[1]), "+f"((c)[2]), "+f"((c)[3]) \
        : "r"((a)[0]), "r"((a)[1]), "r"((a)[2]), "r"((a)[3]), \
          "r"((b)[0]), "r"((b)[1]))

// ===========================================================================
// Fused flash attention (tf32 mma.sync):
//   S[q,k] = (Q^T K), P = exp(S*scale), O[q,d] = P @ V^T, out = O / rowsum
// One CTA per 128-query tile; 8 warps (4 q-rows x 2 cols); 24 key chunks.
// Writes p_val as [d, hw].
// smem (floats): sQ 2x32x136 | sK 2x32x136 | sV 128x132 | sP 128x132 | sL 256
// ===========================================================================
#define SQ_STRIDE 136
#define SV_STRIDE 132
#define ATTN_SMEM_FLOATS (2*32*136 + 2*32*136 + 128*132 + 128*132 + 256)
#define ATTN_SMEM_BYTES  (ATTN_SMEM_FLOATS * 4)

__global__ void __launch_bounds__(256, 1) flash_attn(
    const float* __restrict__ qten, const float* __restrict__ kten,
    const float* __restrict__ valten, float* __restrict__ pvalten)
{
    extern __shared__ float sm[];
    float* sQ = sm;                       // 8704
    float* sK = sQ + 2 * 32 * SQ_STRIDE;  // 8704
    float* sV = sK + 2 * 32 * SQ_STRIDE;  // 16896
    float* sP = sV + 128 * SV_STRIDE;     // 16896
    float* sL = sP + 128 * SV_STRIDE;     // 256

    const uint32_t sQa = (uint32_t)__cvta_generic_to_shared(sQ);
    const uint32_t sKa = (uint32_t)__cvta_generic_to_shared(sK);
    const uint32_t sVa = (uint32_t)__cvta_generic_to_shared(sV);

    const int tid  = threadIdx.x;
    const int lane = tid & 31;
    const int wid  = tid >> 5;
    const int wr   = wid >> 1;          // 0..3 : q-row group (32 rows)
    const int wc   = wid & 1;           // 0..1 : col group (64 cols)
    const int grp  = lane >> 2;         // 0..7
    const int j0   = lane & 3;          // 0..3
    const int z    = blockIdx.y;
    const int q0   = blockIdx.x * 128;

    const float* Qg = qten   + (size_t)z * KQCH  * HWP;
    const float* Kg = kten   + (size_t)z * KQCH  * HWP;
    const float* Vg = valten + (size_t)z * HIDDEN * HWP;
    float*      POg = pvalten + (size_t)z * HIDDEN * HWP;

    sL[tid] = 0.f;   // 256 entries, one per thread

    float oacc[2][8][4];
#pragma unroll
    for (int ma = 0; ma < 2; ma++)
#pragma unroll
        for (int na = 0; na < 8; na++)
#pragma unroll
            for (int e = 0; e < 4; e++) oacc[ma][na][e] = 0.f;

    __syncthreads();

    for (int j = 0; j < 24; j++) {
        const int kp0 = j * 128;

        // --- V tile for this chunk (group 1): 128d x 128k, transfers during S ---
#pragma unroll
        for (int i = 0; i < 16; i++) {
            int idx = tid + i * 256;
            int d = idx >> 5, seg = idx & 31;
            CP16(sVa + (uint32_t)(d * SV_STRIDE + seg * 4) * 4,
                 Vg + (size_t)d * HWP + kp0 + seg * 4);
        }
        CPCOMMIT();

        // --- Q/K c-chunk prologue (chunks 0,1) ---
#pragma unroll
        for (int c = 0; c < 2; c++) {
#pragma unroll
            for (int i = 0; i < 4; i++) {
                int idx = tid + i * 256;
                int cl = idx >> 5, seg = idx & 31;
                uint32_t off = (uint32_t)(c * 32 * SQ_STRIDE + cl * SQ_STRIDE + seg * 4) * 4;
                CP16(sQa + off, Qg + (size_t)(c * 32 + cl) * HWP + q0 + seg * 4);
                CP16(sKa + off, Kg + (size_t)(c * 32 + cl) * HWP + kp0 + seg * 4);
            }
            CPCOMMIT();
        }

        float sacc[2][8][4];
#pragma unroll
        for (int ma = 0; ma < 2; ma++)
#pragma unroll
            for (int na = 0; na < 8; na++)
#pragma unroll
                for (int e = 0; e < 4; e++) sacc[ma][na][e] = 0.f;

        // ======== S phase: 12 c-chunks of 32, double-buffered ========
        for (int cb = 0; cb < 12; cb++) {
            if (cb < 11) { CPWAIT(1); } else { CPWAIT(0); }
            __syncthreads();

            const int b = cb & 1;
            const float* qb = sQ + b * 32 * SQ_STRIDE;
            const float* kb = sK + b * 32 * SQ_STRIDE;

#pragma unroll
            for (int s = 0; s < 4; s++) {
                const int cr = s * 8 + j0;
                uint32_t af[2][4], bf[8][2];
#pragma unroll
                for (int ma = 0; ma < 2; ma++) {
                    const int q = wr * 32 + ma * 16 + grp;
                    af[ma][0] = __float_as_uint(qb[cr * SQ_STRIDE + q]);
                    af[ma][1] = __float_as_uint(qb[cr * SQ_STRIDE + q + 8]);
                    af[ma][2] = __float_as_uint(qb[(cr + 4) * SQ_STRIDE + q]);
                    af[ma][3] = __float_as_uint(qb[(cr + 4) * SQ_STRIDE + q + 8]);
                }
#pragma unroll
                for (int na = 0; na < 8; na++) {
                    const int kc = wc * 64 + na * 8 + grp;
                    bf[na][0] = __float_as_uint(kb[cr * SQ_STRIDE + kc]);
                    bf[na][1] = __float_as_uint(kb[(cr + 4) * SQ_STRIDE + kc]);
                }
#pragma unroll
                for (int ma = 0; ma < 2; ma++)
#pragma unroll
                    for (int na = 0; na < 8; na++)
                        MMA8(sacc[ma][na], af[ma], bf[na]);
            }
            __syncthreads();

            if (cb + 2 < 12) {
                const int cn = cb + 2;
#pragma unroll
                for (int i = 0; i < 4; i++) {
                    int idx = tid + i * 256;
                    int cl = idx >> 5, seg = idx & 31;
                    uint32_t off = (uint32_t)((cb & 1) * 32 * SQ_STRIDE + cl * SQ_STRIDE + seg * 4) * 4;
                    CP16(sQa + off, Qg + (size_t)(cn * 32 + cl) * HWP + q0 + seg * 4);
                    CP16(sKa + off, Kg + (size_t)(cn * 32 + cl) * HWP + kp0 + seg * 4);
                }
                CPCOMMIT();
            }
        }

        // ======== softmax: P = exp(S*scale), row sums ========
        float rs[4] = {0.f, 0.f, 0.f, 0.f};
#pragma unroll
        for (int ma = 0; ma < 2; ma++)
#pragma unroll
            for (int na = 0; na < 8; na++)
#pragma unroll
                for (int e = 0; e < 4; e++) {
                    float p = __expf(sacc[ma][na][e] * SCALE);
                    sacc[ma][na][e] = p;
                    rs[ma * 2 + (e >> 1)] += p;
                }
#pragma unroll
        for (int i = 0; i < 4; i++) {
            rs[i] += __shfl_xor_sync(0xffffffffu, rs[i], 1);
            rs[i] += __shfl_xor_sync(0xffffffffu, rs[i], 2);
        }
        if (j0 == 0) {
#pragma unroll
            for (int ma = 0; ma < 2; ma++) {
                sL[wc * 128 + wr * 32 + ma * 16 + grp]     += rs[ma * 2];
                sL[wc * 128 + wr * 32 + ma * 16 + grp + 8] += rs[ma * 2 + 1];
            }
        }
        // store P to smem (tf32-rounded)
#pragma unroll
        for (int ma = 0; ma < 2; ma++) {
            const int row = wr * 32 + ma * 16 + grp;
#pragma unroll
            for (int na = 0; na < 8; na++) {
                const int col = wc * 64 + na * 8 + 2 * j0;
                uint32_t* p0 = (uint32_t*)&sP[row * SV_STRIDE + col];
                p0[0] = f2tf32(sacc[ma][na][0]);
                p0[1] = f2tf32(sacc[ma][na][1]);
                uint32_t* p1 = (uint32_t*)&sP[(row + 8) * SV_STRIDE + col];
                p1[0] = f2tf32(sacc[ma][na][2]);
                p1[1] = f2tf32(sacc[ma][na][3]);
            }
        }
        CPWAIT(0);        // V tile arrived
        __syncthreads();  // sP + sV visible to all

        // ======== PV phase: O += P @ V^T over this chunk's 128 keys ========
#pragma unroll
        for (int s = 0; s < 16; s++) {
            const int kr = s * 8 + j0;
            uint32_t af[2][4], bf[8][2];
#pragma unroll
            for (int ma = 0; ma < 2; ma++) {
                const int q = wr * 32 + ma * 16 + grp;
                af[ma][0] = __float_as_uint(sP[q * SV_STRIDE + kr]);
                af[ma][1] = __float_as_uint(sP[(q + 8) * SV_STRIDE + kr]);
                af[ma][2] = __float_as_uint(sP[q * SV_STRIDE + kr + 4]);
                af[ma][3] = __float_as_uint(sP[(q + 8) * SV_STRIDE + kr + 4]);
            }
#pragma unroll
            for (int na = 0; na < 8; na++) {
                const int d = wc * 64 + na * 8 + grp;
                bf[na][0] = __float_as_uint(sV[d * SV_STRIDE + kr]);
                bf[na][1] = __float_as_uint(sV[d * SV_STRIDE + kr + 4]);
            }
#pragma unroll
            for (int ma = 0; ma < 2; ma++)
#pragma unroll
                for (int na = 0; na < 8; na++)
                    MMA8(oacc[ma][na], af[ma], bf[na]);
        }
        __syncthreads();  // done reading sP/sV before next chunk rewrites
    }

    // ======== epilogue: normalize, transpose via smem, store [d, hw] ========
    float linv[4];
#pragma unroll
    for (int ma = 0; ma < 2; ma++) {
        const int qlo = wr * 32 + ma * 16 + grp;
        linv[ma * 2]     = 1.f / (sL[qlo] + sL[128 + qlo]);
        linv[ma * 2 + 1] = 1.f / (sL[qlo + 8] + sL[128 + qlo + 8]);
    }
#pragma unroll
    for (int ma = 0; ma < 2; ma++) {
        const int row = wr * 32 + ma * 16 + grp;
#pragma unroll
        for (int na = 0; na < 8; na++) {
            const int col = wc * 64 + na * 8 + 2 * j0;
            sP[row * SV_STRIDE + col]           = oacc[ma][na][0] * linv[ma * 2];
            sP[row * SV_STRIDE + col + 1]       = oacc[ma][na][1] * linv[ma * 2];
            sP[(row + 8) * SV_STRIDE + col]     = oacc[ma][na][2] * linv[ma * 2 + 1];
            sP[(row + 8) * SV_STRIDE + col + 1] = oacc[ma][na][3] * linv[ma * 2 + 1];
        }
    }
    __syncthreads();
#pragma unroll
    for (int idx = tid; idx < 16384; idx += 256) {
        const int d = idx >> 7, q = idx & 127;
        POg[(size_t)d * HWP + q0 + q] = sP[q * SV_STRIDE + d];
    }
}

// ===========================================================================
// CUDA-core SGEMM (1x1 conv) and implicit-GEMM 3x3 convs (unchanged from R2)
// ===========================================================================
template<bool TRANSA>
__global__ void __launch_bounds__(256) sgemm128(
    const float* __restrict__ A, const float* __restrict__ B,
    const float* __restrict__ Res, float* __restrict__ C,
    int M, int N, int Kd, int lda, int ldb, int ldc,
    long long sA, long long sB, long long sC,
    float alpha, int epi)
{
    __shared__ float As[8][128];
    __shared__ float Bs[8][128];

    int z = blockIdx.z;
    A += (long long)z * sA;
    B += (long long)z * sB;
    C += (long long)z * sC;
    if (Res) Res += (long long)z * sC;

    int m0 = blockIdx.y * 128, n0 = blockIdx.x * 128;
    int tid = threadIdx.x;
    int tx = tid & 15, ty = tid >> 4;

    float acc[8][8];
#pragma unroll
    for (int i = 0; i < 8; i++)
#pragma unroll
        for (int j2 = 0; j2 < 8; j2++) acc[i][j2] = 0.f;

    for (int k0 = 0; k0 < Kd; k0 += 8) {
        {
            int kk = tid >> 5, c = (tid & 31) * 4;
            float4 bv = *reinterpret_cast<const float4*>(
                &B[(long long)(k0 + kk) * ldb + n0 + c]);
            Bs[kk][c] = bv.x; Bs[kk][c + 1] = bv.y;
            Bs[kk][c + 2] = bv.z; Bs[kk][c + 3] = bv.w;
        }
        if (TRANSA) {
            int kk = tid >> 5, r = (tid & 31) * 4;
            float4 av = *reinterpret_cast<const float4*>(
                &A[(long long)(k0 + kk) * lda + m0 + r]);
            As[kk][r] = av.x; As[kk][r + 1] = av.y;
            As[kk][r + 2] = av.z; As[kk][r + 3] = av.w;
        } else {
            int r = tid >> 1, c = (tid & 1) * 4;
            float4 av = *reinterpret_cast<const float4*>(
                &A[(long long)(m0 + r) * lda + k0 + c]);
            As[c][r] = av.x; As[c + 1][r] = av.y;
            As[c + 2][r] = av.z; As[c + 3][r] = av.w;
        }
        __syncthreads();

#pragma unroll
        for (int kk = 0; kk < 8; kk++) {
            float a[8], b[8];
#pragma unroll
            for (int i = 0; i < 8; i++) a[i] = As[kk][ty * 8 + i];
#pragma unroll
            for (int j2 = 0; j2 < 8; j2++) b[j2] = Bs[kk][tx * 8 + j2];
#pragma unroll
            for (int i = 0; i < 8; i++)
#pragma unroll
                for (int j2 = 0; j2 < 8; j2++)
                    acc[i][j2] = fmaf(a[i], b[j2], acc[i][j2]);
        }
        __syncthreads();
    }

#pragma unroll
    for (int i = 0; i < 8; i++) {
        int gi = m0 + ty * 8 + i;
#pragma unroll
        for (int j2 = 0; j2 < 8; j2++) {
            int gj = n0 + tx * 8 + j2;
            float vv = acc[i][j2] * alpha;
            if (epi == 1) vv = lrelu(vv);
            else if (epi == 2) vv = Res[(long long)gi * ldc + gj] + lrelu(vv);
            C[(long long)gi * ldc + gj] = vv;
        }
    }
}

template<int DIL>
__global__ void __launch_bounds__(256) conv3x3_gemm(
    const float* __restrict__ in, const float* __restrict__ wt,
    const float* __restrict__ Res, float* __restrict__ out, int epi)
{
    __shared__ float As[8][128];
    __shared__ float Bs[8][64];

    int z = blockIdx.z;
    in  += (long long)z * HIDDEN * HWP;
    out += (long long)z * HIDDEN * HWP;
    const float* Rb = Res ? Res + (long long)z * HIDDEN * HWP : nullptr;

    int n0 = blockIdx.x * 64;
    int tid = threadIdx.x;
    int tx = tid & 15, ty = tid >> 4;

    float acc[8][4];
#pragma unroll
    for (int i = 0; i < 8; i++)
#pragma unroll
        for (int j = 0; j < 4; j++) acc[i][j] = 0.f;

    for (int k0 = 0; k0 < 1152; k0 += 8) {
        int kk = tid >> 5;
        int kglob = k0 + kk;
        int tap = kglob >> 7;
        int ic  = kglob & 127;
        int dy = (tap / 3 - 1) * DIL;
        int dx = (tap % 3 - 1) * DIL;

        {
            int c0 = (tid & 31) * 2;
#pragma unroll
            for (int u = 0; u < 2; u++) {
                int p = n0 + c0 + u;
                int y = p >> 6, x = p & 63;
                int yy = y + dy, xx = x + dx;
                float v = 0.f;
                if ((unsigned)yy < HH && (unsigned)xx < WW)
                    v = in[ic * HWP + yy * WW + xx];
                Bs[kk][c0 + u] = v;
            }
        }
        {
            int r0 = (tid & 31) * 4;
#pragma unroll
            for (int u = 0; u < 4; u++)
                As[kk][r0 + u] = wt[(r0 + u) * 1152 + ic * 9 + tap];
        }
        __syncthreads();

#pragma unroll
        for (int k2 = 0; k2 < 8; k2++) {
            float a[8], b[4];
#pragma unroll
            for (int i = 0; i < 8; i++) a[i] = As[k2][ty * 8 + i];
#pragma unroll
            for (int j = 0; j < 4; j++) b[j] = Bs[k2][tx * 4 + j];
#pragma unroll
            for (int i = 0; i < 8; i++)
#pragma unroll
                for (int j = 0; j < 4; j++)
                    acc[i][j] = fmaf(a[i], b[j], acc[i][j]);
        }
        __syncthreads();
    }

#pragma unroll
    for (int i = 0; i < 8; i++) {
        int gi = ty * 8 + i;
#pragma unroll
        for (int j = 0; j < 4; j++) {
            int gj = n0 + tx * 4 + j;
            float vv = acc[i][j];
            if (epi == 1) vv = lrelu(vv);
            else if (epi == 2) vv = Rb[(long long)gi * HWP + gj] + lrelu(vv);
            out[(long long)gi * HWP + gj] = vv;
        }
    }
}

// ===========================================================================

extern "C" void kernel_launch(void* const* d_in, const int* in_sizes, int n_in,
                              void* d_out, int out_size)
{
    const float* k_in    = (const float*)d_in[0];
    const float* q_in    = (const float*)d_in[1];
    const float* v_in    = (const float*)d_in[2];
    const float* w_value = (const float*)d_in[3];
    const float* w_out   = (const float*)d_in[4];
    const float* w_ff1   = (const float*)d_in[5];
    const float* w_ff2   = (const float*)d_in[6];
    float* out = (float*)d_out;

    float *val, *pval, *v2, *t1;
    cudaGetSymbolAddress((void**)&val,  g_val);
    cudaGetSymbolAddress((void**)&pval, g_pval);
    cudaGetSymbolAddress((void**)&v2,   g_v2);
    cudaGetSymbolAddress((void**)&t1,   g_t1);

    const long long sCHW = (long long)HIDDEN * HWP;

    static int smem_set = 0;
    if (!smem_set) {
        cudaFuncSetAttribute(flash_attn,
                             cudaFuncAttributeMaxDynamicSharedMemorySize,
                             ATTN_SMEM_BYTES);
        smem_set = 1;
    }

    // 1) val = w_value @ v   (1x1 conv)
    sgemm128<false><<<dim3(HWP / 128, 1, NB), 256>>>(
        w_value, v_in, nullptr, val,
        HIDDEN, HWP, HIDDEN, HIDDEN, HWP, HWP,
        0LL, sCHW, sCHW, 1.f, 0);

    // 2+3+4) fused tf32 flash attention -> p_val [d, hw]
    flash_attn<<<dim3(HWP / 128, NB), 256, ATTN_SMEM_BYTES>>>(q_in, k_in, val, pval);

    // 5) v2 = v + lrelu(conv3x3(p_val, w_out, pad=1))
    conv3x3_gemm<1><<<dim3(HWP / 64, 1, NB), 256>>>(pval, w_out, v_in, v2, 2);

    // 6) t1 = lrelu(conv3x3(v2, w_ff1, pad=2, dil=2))
    conv3x3_gemm<2><<<dim3(HWP / 64, 1, NB), 256>>>(v2, w_ff1, nullptr, t1, 1);

    // 7) out = v2 + lrelu(conv3x3(t1, w_ff2, pad=1))
    conv3x3_gemm<1><<<dim3(HWP / 64, 1, NB), 256>>>(t1, w_ff2, v2, out, 2);
}

// round 6
// speedup vs baseline: 3.2640x; 1.6391x over previous
#include <cuda_runtime.h>
#include <cstdint>
#include <math.h>

#define HIDDEN 128
#define KQCH   384
#define HH     48
#define WW     64
#define HWP    3072
#define NB     4
#define SCALE  0.05103103630798288f

// Scratch (allocation-free rule: __device__ globals)
__device__ float g_val[(size_t)NB*HIDDEN*HWP];
__device__ float g_pval[(size_t)NB*HIDDEN*HWP];
__device__ float g_v2[(size_t)NB*HIDDEN*HWP];
__device__ float g_t1[(size_t)NB*HIDDEN*HWP];
__device__ float g_wtT_hi[3][1152*128];
__device__ float g_wtT_lo[3][1152*128];

__device__ __forceinline__ float lrelu(float x) { return x >= 0.f ? x : 0.2f * x; }

// ---------------- PTX helpers -----
__device__ __forceinline__ uint32_t f2tf32(float f) {
    uint32_t u;
    asm("cvt.rna.tf32.f32 %0, %1;" : "=r"(u) : "f"(f));
    return u;
}

#define CP16(dst_u32, src_ptr) \
    asm volatile("cp.async.cg.shared.global [%0], [%1], 16;" \
        :: "r"(dst_u32), "l"(src_ptr))
#define CPCOMMIT() asm volatile("cp.async.commit_group;" ::: "memory")
#define CPWAIT(n)  asm volatile("cp.async.wait_group %0;" :: "n"(n) : "memory")

#define MMA8(c, a, b) \
    asm volatile( \
        "mma.sync.aligned.m16n8k8.row.col.f32.tf32.tf32.f32 " \
        "{%0,%1,%2,%3},{%4,%5,%6,%7},{%8,%9},{%0,%1,%2,%3};" \
        : "+f"((c)[0]), "+f"((c)[1]), "+f"((c)[2]), "+f"((c)[3]) \
        : "r"((a)[0]), "r"((a)[1]), "r"((a)[2]), "r"((a)[3]), \
          "r"((b)[0]), "r"((b)[1]))

// ===========================================================================
// Weight transpose + hi/lo split: k = tap*128 + ic
// ===========================================================================
__global__ void wt_transpose(const float* __restrict__ src,
                             float* __restrict__ dhi, float* __restrict__ dlo)
{
    int idx = blockIdx.x * 256 + threadIdx.x;   // 1152*128 total
    int k = idx >> 7, oc = idx & 127;
    int tap = k >> 7, ic = k & 127;
    float v = src[oc * 1152 + ic * 9 + tap];
    float hi = __uint_as_float(f2tf32(v));
    float lo = __uint_as_float(f2tf32(v - hi));
    dhi[idx] = hi;
    dlo[idx] = lo;
}

// ===========================================================================
// Fused flash attention (tf32 mma.sync) — unchanged from R4 (passing, 2.8e-5)
// ===========================================================================
#define SQ_STRIDE 136
#define SV_STRIDE 132
#define ATTN_SMEM_FLOATS (2*32*136 + 2*32*136 + 128*132 + 128*132 + 256)
#define ATTN_SMEM_BYTES  (ATTN_SMEM_FLOATS * 4)

__global__ void __launch_bounds__(256, 1) flash_attn(
    const float* __restrict__ qten, const float* __restrict__ kten,
    const float* __restrict__ valten, float* __restrict__ pvalten)
{
    extern __shared__ float sm[];
    float* sQ = sm;
    float* sK = sQ + 2 * 32 * SQ_STRIDE;
    float* sV = sK + 2 * 32 * SQ_STRIDE;
    float* sP = sV + 128 * SV_STRIDE;
    float* sL = sP + 128 * SV_STRIDE;

    const uint32_t sQa = (uint32_t)__cvta_generic_to_shared(sQ);
    const uint32_t sKa = (uint32_t)__cvta_generic_to_shared(sK);
    const uint32_t sVa = (uint32_t)__cvta_generic_to_shared(sV);

    const int tid  = threadIdx.x;
    const int lane = tid & 31;
    const int wid  = tid >> 5;
    const int wr   = wid >> 1;
    const int wc   = wid & 1;
    const int grp  = lane >> 2;
    const int j0   = lane & 3;
    const int z    = blockIdx.y;
    const int q0   = blockIdx.x * 128;

    const float* Qg = qten   + (size_t)z * KQCH  * HWP;
    const float* Kg = kten   + (size_t)z * KQCH  * HWP;
    const float* Vg = valten + (size_t)z * HIDDEN * HWP;
    float*      POg = pvalten + (size_t)z * HIDDEN * HWP;

    sL[tid] = 0.f;

    float oacc[2][8][4];
#pragma unroll
    for (int ma = 0; ma < 2; ma++)
#pragma unroll
        for (int na = 0; na < 8; na++)
#pragma unroll
            for (int e = 0; e < 4; e++) oacc[ma][na][e] = 0.f;

    __syncthreads();

    for (int j = 0; j < 24; j++) {
        const int kp0 = j * 128;

#pragma unroll
        for (int i = 0; i < 16; i++) {
            int idx = tid + i * 256;
            int d = idx >> 5, seg = idx & 31;
            CP16(sVa + (uint32_t)(d * SV_STRIDE + seg * 4) * 4,
                 Vg + (size_t)d * HWP + kp0 + seg * 4);
        }
        CPCOMMIT();

#pragma unroll
        for (int c = 0; c < 2; c++) {
#pragma unroll
            for (int i = 0; i < 4; i++) {
                int idx = tid + i * 256;
                int cl = idx >> 5, seg = idx & 31;
                uint32_t off = (uint32_t)(c * 32 * SQ_STRIDE + cl * SQ_STRIDE + seg * 4) * 4;
                CP16(sQa + off, Qg + (size_t)(c * 32 + cl) * HWP + q0 + seg * 4);
                CP16(sKa + off, Kg + (size_t)(c * 32 + cl) * HWP + kp0 + seg * 4);
            }
            CPCOMMIT();
        }

        float sacc[2][8][4];
#pragma unroll
        for (int ma = 0; ma < 2; ma++)
#pragma unroll
            for (int na = 0; na < 8; na++)
#pragma unroll
                for (int e = 0; e < 4; e++) sacc[ma][na][e] = 0.f;

        for (int cb = 0; cb < 12; cb++) {
            if (cb < 11) { CPWAIT(1); } else { CPWAIT(0); }
            __syncthreads();

            const int b = cb & 1;
            const float* qb = sQ + b * 32 * SQ_STRIDE;
            const float* kb = sK + b * 32 * SQ_STRIDE;

#pragma unroll
            for (int s = 0; s < 4; s++) {
                const int cr = s * 8 + j0;
                uint32_t af[2][4], bf[8][2];
#pragma unroll
                for (int ma = 0; ma < 2; ma++) {
                    const int q = wr * 32 + ma * 16 + grp;
                    af[ma][0] = __float_as_uint(qb[cr * SQ_STRIDE + q]);
                    af[ma][1] = __float_as_uint(qb[cr * SQ_STRIDE + q + 8]);
                    af[ma][2] = __float_as_uint(qb[(cr + 4) * SQ_STRIDE + q]);
                    af[ma][3] = __float_as_uint(qb[(cr + 4) * SQ_STRIDE + q + 8]);
                }
#pragma unroll
                for (int na = 0; na < 8; na++) {
                    const int kc = wc * 64 + na * 8 + grp;
                    bf[na][0] = __float_as_uint(kb[cr * SQ_STRIDE + kc]);
                    bf[na][1] = __float_as_uint(kb[(cr + 4) * SQ_STRIDE + kc]);
                }
#pragma unroll
                for (int ma = 0; ma < 2; ma++)
#pragma unroll
                    for (int na = 0; na < 8; na++)
                        MMA8(sacc[ma][na], af[ma], bf[na]);
            }
            __syncthreads();

            if (cb + 2 < 12) {
                const int cn = cb + 2;
#pragma unroll
                for (int i = 0; i < 4; i++) {
                    int idx = tid + i * 256;
                    int cl = idx >> 5, seg = idx & 31;
                    uint32_t off = (uint32_t)((cb & 1) * 32 * SQ_STRIDE + cl * SQ_STRIDE + seg * 4) * 4;
                    CP16(sQa + off, Qg + (size_t)(cn * 32 + cl) * HWP + q0 + seg * 4);
                    CP16(sKa + off, Kg + (size_t)(cn * 32 + cl) * HWP + kp0 + seg * 4);
                }
                CPCOMMIT();
            }
        }

        float rs[4] = {0.f, 0.f, 0.f, 0.f};
#pragma unroll
        for (int ma = 0; ma < 2; ma++)
#pragma unroll
            for (int na = 0; na < 8; na++)
#pragma unroll
                for (int e = 0; e < 4; e++) {
                    float p = __expf(sacc[ma][na][e] * SCALE);
                    sacc[ma][na][e] = p;
                    rs[ma * 2 + (e >> 1)] += p;
                }
#pragma unroll
        for (int i = 0; i < 4; i++) {
            rs[i] += __shfl_xor_sync(0xffffffffu, rs[i], 1);
            rs[i] += __shfl_xor_sync(0xffffffffu, rs[i], 2);
        }
        if (j0 == 0) {
#pragma unroll
            for (int ma = 0; ma < 2; ma++) {
                sL[wc * 128 + wr * 32 + ma * 16 + grp]     += rs[ma * 2];
                sL[wc * 128 + wr * 32 + ma * 16 + grp + 8] += rs[ma * 2 + 1];
            }
        }
#pragma unroll
        for (int ma = 0; ma < 2; ma++) {
            const int row = wr * 32 + ma * 16 + grp;
#pragma unroll
            for (int na = 0; na < 8; na++) {
                const int col = wc * 64 + na * 8 + 2 * j0;
                uint32_t* p0 = (uint32_t*)&sP[row * SV_STRIDE + col];
                p0[0] = f2tf32(sacc[ma][na][0]);
                p0[1] = f2tf32(sacc[ma][na][1]);
                uint32_t* p1 = (uint32_t*)&sP[(row + 8) * SV_STRIDE + col];
                p1[0] = f2tf32(sacc[ma][na][2]);
                p1[1] = f2tf32(sacc[ma][na][3]);
            }
        }
        CPWAIT(0);
        __syncthreads();

#pragma unroll
        for (int s = 0; s < 16; s++) {
            const int kr = s * 8 + j0;
            uint32_t af[2][4], bf[8][2];
#pragma unroll
            for (int ma = 0; ma < 2; ma++) {
                const int q = wr * 32 + ma * 16 + grp;
                af[ma][0] = __float_as_uint(sP[q * SV_STRIDE + kr]);
                af[ma][1] = __float_as_uint(sP[(q + 8) * SV_STRIDE + kr]);
                af[ma][2] = __float_as_uint(sP[q * SV_STRIDE + kr + 4]);
                af[ma][3] = __float_as_uint(sP[(q + 8) * SV_STRIDE + kr + 4]);
            }
#pragma unroll
            for (int na = 0; na < 8; na++) {
                const int d = wc * 64 + na * 8 + grp;
                bf[na][0] = __float_as_uint(sV[d * SV_STRIDE + kr]);
                bf[na][1] = __float_as_uint(sV[d * SV_STRIDE + kr + 4]);
            }
#pragma unroll
            for (int ma = 0; ma < 2; ma++)
#pragma unroll
                for (int na = 0; na < 8; na++)
                    MMA8(oacc[ma][na], af[ma], bf[na]);
        }
        __syncthreads();
    }

    float linv[4];
#pragma unroll
    for (int ma = 0; ma < 2; ma++) {
        const int qlo = wr * 32 + ma * 16 + grp;
        linv[ma * 2]     = 1.f / (sL[qlo] + sL[128 + qlo]);
        linv[ma * 2 + 1] = 1.f / (sL[qlo + 8] + sL[128 + qlo + 8]);
    }
#pragma unroll
    for (int ma = 0; ma < 2; ma++) {
        const int row = wr * 32 + ma * 16 + grp;
#pragma unroll
        for (int na = 0; na < 8; na++) {
            const int col = wc * 64 + na * 8 + 2 * j0;
            sP[row * SV_STRIDE + col]           = oacc[ma][na][0] * linv[ma * 2];
            sP[row * SV_STRIDE + col + 1]       = oacc[ma][na][1] * linv[ma * 2];
            sP[(row + 8) * SV_STRIDE + col]     = oacc[ma][na][2] * linv[ma * 2 + 1];
            sP[(row + 8) * SV_STRIDE + col + 1] = oacc[ma][na][3] * linv[ma * 2 + 1];
        }
    }
    __syncthreads();
#pragma unroll
    for (int idx = tid; idx < 16384; idx += 256) {
        const int d = idx >> 7, q = idx & 127;
        POg[(size_t)d * HWP + q0 + q] = sP[q * SV_STRIDE + d];
    }
}

// ===========================================================================
// 3x3 conv via 3xTF32 mma.sync implicit GEMM (hi/lo error compensation).
// M=128 oc x N=128 pixels x K=1152, 36 k-chunks, 3 MMA passes per chunk:
//   acc += Ahi*Bhi + Ahi*Blo + Alo*Bhi
// ===========================================================================
#define CS 136
#define CONV_SMEM_BYTES (8 * 32 * CS * 4)   // Ahi0,Ahi1,Alo0,Alo1,Bhi0,Bhi1,Blo0,Blo1

template<int DIL>
__global__ void __launch_bounds__(256, 1) conv_mma(
    const float* __restrict__ in,
    const float* __restrict__ wtHi, const float* __restrict__ wtLo,
    const float* __restrict__ Res, float* __restrict__ out, int epi)
{
    extern __shared__ float sm[];
    float* sAhi[2] = { sm,               sm + 32 * CS };
    float* sAlo[2] = { sm + 2 * 32 * CS, sm + 3 * 32 * CS };
    float* sBhi[2] = { sm + 4 * 32 * CS, sm + 5 * 32 * CS };
    float* sBlo[2] = { sm + 6 * 32 * CS, sm + 7 * 32 * CS };
    uint32_t sAhia[2], sAloa[2];
#pragma unroll
    for (int b = 0; b < 2; b++) {
        sAhia[b] = (uint32_t)__cvta_generic_to_shared(sAhi[b]);
        sAloa[b] = (uint32_t)__cvta_generic_to_shared(sAlo[b]);
    }

    const int tid  = threadIdx.x;
    const int lane = tid & 31;
    const int wid  = tid >> 5;
    const int wr   = wid >> 1;
    const int wc   = wid & 1;
    const int grp  = lane >> 2;
    const int j0   = lane & 3;
    const int z    = blockIdx.y;
    const int n0   = blockIdx.x * 128;

    const float* inb = in + (size_t)z * HIDDEN * HWP;
    float* outb = out + (size_t)z * HIDDEN * HWP;
    const float* Rb = Res ? Res + (size_t)z * HIDDEN * HWP : nullptr;

    float acc[2][8][4];
#pragma unroll
    for (int ma = 0; ma < 2; ma++)
#pragma unroll
        for (int na = 0; na < 8; na++)
#pragma unroll
            for (int e = 0; e < 4; e++) acc[ma][na][e] = 0.f;

    float breg[16];

    auto loadB = [&](int c) {
        const int tap = c >> 2, ic0 = (c & 3) * 32;
        const int dy = (tap / 3 - 1) * DIL, dx = (tap % 3 - 1) * DIL;
#pragma unroll
        for (int i = 0; i < 16; i++) {
            int idx = i * 256 + tid;
            int row = idx >> 7, col = idx & 127;
            int p = n0 + col;
            int y = p >> 6, x = p & 63;
            int yy = y + dy, xx = x + dx;
            float v = 0.f;
            if ((unsigned)yy < HH && (unsigned)xx < WW)
                v = inb[(size_t)(ic0 + row) * HWP + yy * WW + xx];
            breg[i] = v;
        }
    };
    auto storeB = [&](int buf) {
#pragma unroll
        for (int i = 0; i < 16; i++) {
            int idx = i * 256 + tid;
            int row = idx >> 7, col = idx & 127;
            float v = breg[i];
            float hi = __uint_as_float(f2tf32(v));
            float lo = __uint_as_float(f2tf32(v - hi));
            sBhi[buf][row * CS + col] = hi;
            sBlo[buf][row * CS + col] = lo;
        }
    };
    auto cpA = [&](int c, int buf) {
        const float* bh = wtHi + (size_t)c * 32 * 128;
        const float* bl = wtLo + (size_t)c * 32 * 128;
#pragma unroll
        for (int i = 0; i < 4; i++) {
            int idx = i * 256 + tid;
            int row = idx >> 5, col4 = (idx & 31) * 4;
            uint32_t off = (uint32_t)(row * CS + col4) * 4;
            CP16(sAhia[buf] + off, bh + idx * 4);
            CP16(sAloa[buf] + off, bl + idx * 4);
        }
    };

    loadB(0); storeB(0); cpA(0, 0); CPCOMMIT();
    loadB(1); cpA(1, 1); CPCOMMIT();
    CPWAIT(1);
    __syncthreads();
    storeB(1);
    loadB(2);

    for (int c = 0; c < 36; c++) {
        const int b = c & 1;

#pragma unroll
        for (int p = 0; p < 3; p++) {
            const float* ab = (p == 2) ? sAlo[b] : sAhi[b];
            const float* bb = (p == 1) ? sBlo[b] : sBhi[b];
#pragma unroll
            for (int s = 0; s < 4; s++) {
                const int cr = s * 8 + j0;
                uint32_t af[2][4], bf[8][2];
#pragma unroll
                for (int ma = 0; ma < 2; ma++) {
                    const int m = wr * 32 + ma * 16 + grp;
                    af[ma][0] = __float_as_uint(ab[cr * CS + m]);
                    af[ma][1] = __float_as_uint(ab[cr * CS + m + 8]);
                    af[ma][2] = __float_as_uint(ab[(cr + 4) * CS + m]);
                    af[ma][3] = __float_as_uint(ab[(cr + 4) * CS + m + 8]);
                }
#pragma unroll
                for (int na = 0; na < 8; na++) {
                    const int n = wc * 64 + na * 8 + grp;
                    bf[na][0] = __float_as_uint(bb[cr * CS + n]);
                    bf[na][1] = __float_as_uint(bb[(cr + 4) * CS + n]);
                }
#pragma unroll
                for (int ma = 0; ma < 2; ma++)
#pragma unroll
                    for (int na = 0; na < 8; na++)
                        MMA8(acc[ma][na], af[ma], bf[na]);
            }
        }
        __syncthreads();

        if (c + 2 < 36) {
            storeB((c + 2) & 1);
            cpA(c + 2, (c + 2) & 1);
            CPCOMMIT();
            if (c + 3 < 36) loadB(c + 3);
            CPWAIT(1);
        } else {
            CPWAIT(0);
        }
        __syncthreads();
    }

#pragma unroll
    for (int ma = 0; ma < 2; ma++) {
        const int r0 = wr * 32 + ma * 16 + grp;
#pragma unroll
        for (int na = 0; na < 8; na++) {
            const int cc = n0 + wc * 64 + na * 8 + 2 * j0;
#pragma unroll
            for (int h = 0; h < 2; h++) {
                const int r = r0 + h * 8;
#pragma unroll
                for (int e = 0; e < 2; e++) {
                    float vv = acc[ma][na][h * 2 + e];
                    vv = lrelu(vv);
                    if (epi == 2) vv += Rb[(size_t)r * HWP + cc + e];
                    outb[(size_t)r * HWP + cc + e] = vv;
                }
            }
        }
    }
}

// ===========================================================================
// CUDA-core SGEMM for the 1x1 conv (fp32, exact)
// ===========================================================================
__global__ void __launch_bounds__(256) sgemm_1x1(
    const float* __restrict__ A, const float* __restrict__ B,
    float* __restrict__ C)
{
    __shared__ float As[8][128];
    __shared__ float Bs[8][128];

    int z = blockIdx.z;
    B += (long long)z * HIDDEN * HWP;
    C += (long long)z * HIDDEN * HWP;

    int n0 = blockIdx.x * 128;
    int tid = threadIdx.x;
    int tx = tid & 15, ty = tid >> 4;

    float acc[8][8];
#pragma unroll
    for (int i = 0; i < 8; i++)
#pragma unroll
        for (int j2 = 0; j2 < 8; j2++) acc[i][j2] = 0.f;

    for (int k0 = 0; k0 < HIDDEN; k0 += 8) {
        {
            int kk = tid >> 5, c = (tid & 31) * 4;
            float4 bv = *reinterpret_cast<const float4*>(
                &B[(long long)(k0 + kk) * HWP + n0 + c]);
            Bs[kk][c] = bv.x; Bs[kk][c + 1] = bv.y;
            Bs[kk][c + 2] = bv.z; Bs[kk][c + 3] = bv.w;
        }
        {
            int r = tid >> 1, c = (tid & 1) * 4;
            float4 av = *reinterpret_cast<const float4*>(
                &A[(long long)r * HIDDEN + k0 + c]);
            As[c][r] = av.x; As[c + 1][r] = av.y;
            As[c + 2][r] = av.z; As[c + 3][r] = av.w;
        }
        __syncthreads();

#pragma unroll
        for (int kk = 0; kk < 8; kk++) {
            float a[8], b[8];
#pragma unroll
            for (int i = 0; i < 8; i++) a[i] = As[kk][ty * 8 + i];
#pragma unroll
            for (int j2 = 0; j2 < 8; j2++) b[j2] = Bs[kk][tx * 8 + j2];
#pragma unroll
            for (int i = 0; i < 8; i++)
#pragma unroll
                for (int j2 = 0; j2 < 8; j2++)
                    acc[i][j2] = fmaf(a[i], b[j2], acc[i][j2]);
        }
        __syncthreads();
    }

#pragma unroll
    for (int i = 0; i < 8; i++) {
        int gi = ty * 8 + i;
#pragma unroll
        for (int j2 = 0; j2 < 8; j2++)
            C[(long long)gi * HWP + n0 + tx * 8 + j2] = acc[i][j2];
    }
}

// ===========================================================================

extern "C" void kernel_launch(void* const* d_in, const int* in_sizes, int n_in,
                              void* d_out, int out_size)
{
    const float* k_in    = (const float*)d_in[0];
    const float* q_in    = (const float*)d_in[1];
    const float* v_in    = (const float*)d_in[2];
    const float* w_value = (const float*)d_in[3];
    const float* w_out   = (const float*)d_in[4];
    const float* w_ff1   = (const float*)d_in[5];
    const float* w_ff2   = (const float*)d_in[6];
    float* out = (float*)d_out;

    float *val, *pval, *v2, *t1, *wtHi, *wtLo;
    cudaGetSymbolAddress((void**)&val,  g_val);
    cudaGetSymbolAddress((void**)&pval, g_pval);
    cudaGetSymbolAddress((void**)&v2,   g_v2);
    cudaGetSymbolAddress((void**)&t1,   g_t1);
    cudaGetSymbolAddress((void**)&wtHi, g_wtT_hi);
    cudaGetSymbolAddress((void**)&wtLo, g_wtT_lo);
    const int WSZ = 1152 * 128;

    static int attr_set = 0;
    if (!attr_set) {
        cudaFuncSetAttribute(flash_attn,
            cudaFuncAttributeMaxDynamicSharedMemorySize, ATTN_SMEM_BYTES);
        cudaFuncSetAttribute(conv_mma<1>,
            cudaFuncAttributeMaxDynamicSharedMemorySize, CONV_SMEM_BYTES);
        cudaFuncSetAttribute(conv_mma<2>,
            cudaFuncAttributeMaxDynamicSharedMemorySize, CONV_SMEM_BYTES);
        attr_set = 1;
    }

    // 0) weight transposes + hi/lo split (tiny)
    wt_transpose<<<WSZ / 256, 256>>>(w_out, wtHi,           wtLo);
    wt_transpose<<<WSZ / 256, 256>>>(w_ff1, wtHi + WSZ,     wtLo + WSZ);
    wt_transpose<<<WSZ / 256, 256>>>(w_ff2, wtHi + 2 * WSZ, wtLo + 2 * WSZ);

    // 1) val = w_value @ v (1x1 conv, fp32)
    sgemm_1x1<<<dim3(HWP / 128, 1, NB), 256>>>(w_value, v_in, val);

    // 2) fused tf32 flash attention -> p_val [d, hw]
    flash_attn<<<dim3(HWP / 128, NB), 256, ATTN_SMEM_BYTES>>>(q_in, k_in, val, pval);

    // 3) v2 = v + lrelu(conv3x3(p_val, w_out, pad=1))   [3xTF32]
    conv_mma<1><<<dim3(HWP / 128, NB), 256, CONV_SMEM_BYTES>>>(
        pval, wtHi, wtLo, v_in, v2, 2);

    // 4) t1 = lrelu(conv3x3(v2, w_ff1, pad=2, dil=2))   [3xTF32]
    conv_mma<2><<<dim3(HWP / 128, NB), 256, CONV_SMEM_BYTES>>>(
        v2, wtHi + WSZ, wtLo + WSZ, nullptr, t1, 1);

    // 5) out = v2 + lrelu(conv3x3(t1, w_ff2, pad=1))    [3xTF32]
    conv_mma<1><<<dim3(HWP / 128, NB), 256, CONV_SMEM_BYTES>>>(
        t1, wtHi + 2 * WSZ, wtLo + 2 * WSZ, v2, out, 2);
}